// round 2
// baseline (speedup 1.0000x reference)
#include <cuda_runtime.h>

#define BATCH    512
#define TLEN     2048
#define CH       34      // true channel count (2*17)
#define P        36      // padded homogeneous dim (35 -> 36)
#define PP       37      // row pitch (bank-conflict-free)
#define TT       128     // t-tile for Gram phase
#define NBLK     45      // symmetric 4x4 blocks over 36 (9x9 grid, bc >= br)
#define TG       5       // threads (t-phases) per block
#define NTHREADS 256
#define CT       256     // t-chunk for pointwise kernel

// Per-batch fused head matrix: W1f[b][16][35] (homogeneous: col 34 = bias)
__device__ float g_W1f[BATCH * 16 * 35];

// ---------------- 36x36 shared-memory matmuls (216 active threads) ----------

// D = A * B
__device__ __forceinline__ void mm_nn(float (*D)[PP], const float (*A)[PP],
                                      const float (*B)[PP], int tid) {
    if (tid < 216) {
        int r  = tid % P;
        int c0 = (tid / P) * 6;
        float a0 = 0.f, a1 = 0.f, a2 = 0.f, a3 = 0.f, a4 = 0.f, a5 = 0.f;
#pragma unroll
        for (int k = 0; k < P; k++) {
            float a = A[r][k];
            a0 += a * B[k][c0 + 0];
            a1 += a * B[k][c0 + 1];
            a2 += a * B[k][c0 + 2];
            a3 += a * B[k][c0 + 3];
            a4 += a * B[k][c0 + 4];
            a5 += a * B[k][c0 + 5];
        }
        D[r][c0 + 0] = a0; D[r][c0 + 1] = a1; D[r][c0 + 2] = a2;
        D[r][c0 + 3] = a3; D[r][c0 + 4] = a4; D[r][c0 + 5] = a5;
    }
    __syncthreads();
}

// D = A * B^T
__device__ __forceinline__ void mm_nt(float (*D)[PP], const float (*A)[PP],
                                      const float (*B)[PP], int tid) {
    if (tid < 216) {
        int r  = tid % P;
        int c0 = (tid / P) * 6;
        float a0 = 0.f, a1 = 0.f, a2 = 0.f, a3 = 0.f, a4 = 0.f, a5 = 0.f;
#pragma unroll
        for (int k = 0; k < P; k++) {
            float a = A[r][k];
            a0 += a * B[c0 + 0][k];
            a1 += a * B[c0 + 1][k];
            a2 += a * B[c0 + 2][k];
            a3 += a * B[c0 + 3][k];
            a4 += a * B[c0 + 4][k];
            a5 += a * B[c0 + 5][k];
        }
        D[r][c0 + 0] = a0; D[r][c0 + 1] = a1; D[r][c0 + 2] = a2;
        D[r][c0 + 3] = a3; D[r][c0 + 4] = a4; D[r][c0 + 5] = a5;
    }
    __syncthreads();
}

// Stage homogeneous weight: W[r<34][c<34] = w, W[r<34][34] = bias, W[34][34] = 1
__device__ __forceinline__ void stage_w(float (*W)[PP], const float* __restrict__ w,
                                        const float* __restrict__ bias, int tid) {
    for (int i = tid; i < P * PP; i += NTHREADS) {
        int r = i / PP, c = i % PP;
        float v = 0.f;
        if (r < CH && c < CH)       v = w[r * CH + c];
        else if (r < CH && c == CH) v = bias[r];
        else if (r == CH && c == CH) v = 1.f;
        W[r][c] = v;
    }
    __syncthreads();
}

// ---------------- Kernel AB: Gram stats + all attention-layer math ----------

__global__ void __launch_bounds__(NTHREADS) kernel_ab(
    const float* __restrict__ x,
    const float* __restrict__ wq, const float* __restrict__ bq,
    const float* __restrict__ wk, const float* __restrict__ bk,
    const float* __restrict__ wv, const float* __restrict__ bv,
    const float* __restrict__ w1, const float* __restrict__ b1,
    const float* __restrict__ gamma, const float* __restrict__ beta,
    const float* __restrict__ mean, const float* __restrict__ var)
{
    __shared__ __align__(16) float smem[8][P][PP];
    float (*S)[PP]   = smem[0];
    float (*A)[PP]   = smem[1];
    float (*T1)[PP]  = smem[2];
    float (*G)[PP]   = smem[3];
    float (*M)[PP]   = smem[4];
    float (*W0)[PP]  = smem[5];
    float (*Wk_)[PP] = smem[6];
    float (*Wv_)[PP] = smem[7];
    // Phase-A tile buffer overlaps A..Wv_ region (only S must survive phase A)
    float (*Hs)[P] = reinterpret_cast<float(*)[P]>(&smem[1][0][0]);

    int tid = threadIdx.x;
    int b   = blockIdx.x;

    // zero S accumulator
    for (int i = tid; i < P * PP; i += NTHREADS) (&S[0][0])[i] = 0.f;

    bool act = (tid < NBLK * TG);
    int br = 0, bc = 0, sub = 0;
    if (act) {
        int blk = tid / TG;
        sub = tid % TG;
        int k = blk, r = 0;
        while (k >= 9 - r) { k -= 9 - r; r++; }
        br = r; bc = r + k;
    }
    float acc[16];
#pragma unroll
    for (int i = 0; i < 16; i++) acc[i] = 0.f;

    const float* xb = x + (size_t)b * 2 * TLEN * 17;

    // -------- Phase A: S = sum_t h' h'^T  (h' homogeneous: coord 34 = 1) ----
    for (int t0 = 0; t0 < TLEN; t0 += TT) {
        __syncthreads();
        // coalesced stage of x tile -> Hs[t][ch], ch = c*17+v
#pragma unroll
        for (int c = 0; c < 2; c++) {
            const float* src = xb + (size_t)c * TLEN * 17 + (size_t)t0 * 17;
            for (int i = tid; i < TT * 17; i += NTHREADS)
                Hs[i / 17][c * 17 + i % 17] = src[i];
        }
        for (int i = tid; i < TT; i += NTHREADS) { Hs[i][34] = 1.f; Hs[i][35] = 0.f; }
        __syncthreads();

        if (act) {
            for (int t = sub; t < TT; t += TG) {
                float4 av  = *reinterpret_cast<const float4*>(&Hs[t][4 * br]);
                float4 bv4 = *reinterpret_cast<const float4*>(&Hs[t][4 * bc]);
                acc[0]  += av.x * bv4.x; acc[1]  += av.x * bv4.y;
                acc[2]  += av.x * bv4.z; acc[3]  += av.x * bv4.w;
                acc[4]  += av.y * bv4.x; acc[5]  += av.y * bv4.y;
                acc[6]  += av.y * bv4.z; acc[7]  += av.y * bv4.w;
                acc[8]  += av.z * bv4.x; acc[9]  += av.z * bv4.y;
                acc[10] += av.z * bv4.z; acc[11] += av.z * bv4.w;
                acc[12] += av.w * bv4.x; acc[13] += av.w * bv4.y;
                acc[14] += av.w * bv4.z; acc[15] += av.w * bv4.w;
            }
        }
    }
    __syncthreads();
    if (act) {
#pragma unroll
        for (int i = 0; i < 4; i++)
#pragma unroll
            for (int j = 0; j < 4; j++)
                atomicAdd(&S[4 * br + i][4 * bc + j], acc[i * 4 + j]);
    }
    __syncthreads();
    // mirror lower triangle
    for (int i = tid; i < P * P; i += NTHREADS) {
        int r = i / P, c = i % P;
        if (r > c) S[r][c] = S[c][r];
    }
    __syncthreads();

    // -------- Phase B: 3 attention layers in homogeneous coordinates --------
    float scale = rsqrtf((float)TLEN);

    for (int layer = 0; layer < 3; layer++) {
        stage_w(W0,  wq + layer * CH * CH, bq + layer * CH, tid);
        stage_w(Wk_, wk + layer * CH * CH, bk + layer * CH, tid);
        stage_w(Wv_, wv + layer * CH * CH, bv + layer * CH, tid);

        mm_nn(T1, W0, S, tid);    // T1 = Wq' S
        mm_nt(G, T1, Wk_, tid);   // G  = Wq' S Wk'^T  (= Q K^T incl. biases)

        // row softmax over d<34 with scale, then sanitize homogeneous rows
        if (tid < CH) {
            float mx = -1e30f;
            for (int c = 0; c < CH; c++) mx = fmaxf(mx, G[tid][c] * scale);
            float s = 0.f;
            for (int c = 0; c < CH; c++) {
                float e = expf(G[tid][c] * scale - mx);
                G[tid][c] = e; s += e;
            }
            float inv = 1.f / s;
            for (int c = 0; c < CH; c++) G[tid][c] *= inv;
            G[tid][34] = 0.f; G[tid][35] = 0.f;
        } else if (tid == CH) {
            for (int c = 0; c < PP; c++) { G[34][c] = 0.f; G[35][c] = 0.f; }
            G[34][34] = 1.f;
        }
        __syncthreads();

        mm_nn(M, G, Wv_, tid);    // M = attn' Wv''  (affine map for this layer)

        if (layer < 2) {          // propagate statistics: S <- M S M^T
            mm_nn(T1, M, S, tid);
            mm_nt(S, T1, M, tid);
        }

        if (layer == 0) {
            for (int i = tid; i < P * PP; i += NTHREADS) (&A[0][0])[i] = (&M[0][0])[i];
            __syncthreads();
        } else if (layer == 1) {
            mm_nn(T1, M, A, tid); // A <- M2 * M1
            for (int i = tid; i < P * PP; i += NTHREADS) (&A[0][0])[i] = (&T1[0][0])[i];
            __syncthreads();
        } else {
            // Fold conv1 + BatchNorm into homogeneous 16x35 W1h, stage into W0
            for (int i = tid; i < P * PP; i += NTHREADS) {
                int r = i / PP, c = i % PP;
                float v = 0.f;
                if (r < 16) {
                    float iv = gamma[r] * rsqrtf(var[r] + 1e-5f);
                    if (c < CH)       v = iv * w1[r * CH + c];
                    else if (c == CH) v = iv * (b1[r] - mean[r]) + beta[r];
                }
                W0[r][c] = v;
            }
            __syncthreads();
            mm_nn(T1, W0, M, tid); // R   = W1h * M3
            mm_nn(G, T1, A, tid);  // W1f = R * (M2 M1)
            for (int i = tid; i < 16 * 35; i += NTHREADS)
                g_W1f[b * 16 * 35 + i] = G[i / 35][i % 35];
        }
    }
}

// ---------------- Kernel C: pointwise head over every (b, t) ----------------

__global__ void __launch_bounds__(CT) kernel_c(
    const float* __restrict__ x,
    const float* __restrict__ w2, const float* __restrict__ b2,
    float* __restrict__ out)
{
    __shared__ float Wf[16][35];
    __shared__ float w2s[48];
    __shared__ float b2s[3];
    __shared__ float Hc[CT][37];   // pitch 37 -> conflict-free column reads

    int tid = threadIdx.x;
    int b   = blockIdx.y;
    int t0  = blockIdx.x * CT;

    for (int i = tid; i < 16 * 35; i += CT) (&Wf[0][0])[i] = g_W1f[b * 16 * 35 + i];
    if (tid < 48) w2s[tid] = w2[tid];
    if (tid < 3)  b2s[tid] = b2[tid];
#pragma unroll
    for (int c = 0; c < 2; c++) {
        const float* src = x + ((size_t)(b * 2 + c) * TLEN + t0) * 17;
        for (int i = tid; i < CT * 17; i += CT)
            Hc[i / 17][c * 17 + i % 17] = src[i];
    }
    __syncthreads();

    float u[16];
#pragma unroll
    for (int o = 0; o < 16; o++) u[o] = Wf[o][34];   // homogeneous bias column
#pragma unroll
    for (int c = 0; c < CH; c++) {
        float hv = Hc[tid][c];
#pragma unroll
        for (int o = 0; o < 16; o++) u[o] += Wf[o][c] * hv;
    }
#pragma unroll
    for (int o = 0; o < 16; o++) u[o] = (u[o] > 0.f) ? u[o] : 0.01f * u[o];

#pragma unroll
    for (int j = 0; j < 3; j++) {
        float s = b2s[j];
#pragma unroll
        for (int o = 0; o < 16; o++) s += w2s[j * 16 + o] * u[o];
        out[(size_t)(b * 3 + j) * TLEN + t0 + tid] = s;
    }
}

// ---------------------------------------------------------------------------

extern "C" void kernel_launch(void* const* d_in, const int* in_sizes, int n_in,
                              void* d_out, int out_size) {
    const float* x     = (const float*)d_in[0];
    const float* wq    = (const float*)d_in[1];
    const float* bq    = (const float*)d_in[2];
    const float* wk    = (const float*)d_in[3];
    const float* bk    = (const float*)d_in[4];
    const float* wv    = (const float*)d_in[5];
    const float* bv    = (const float*)d_in[6];
    const float* w1    = (const float*)d_in[7];
    const float* b1    = (const float*)d_in[8];
    const float* gamma = (const float*)d_in[9];
    const float* beta  = (const float*)d_in[10];
    const float* mean  = (const float*)d_in[11];
    const float* var   = (const float*)d_in[12];
    const float* w2    = (const float*)d_in[13];
    const float* b2    = (const float*)d_in[14];
    float* out = (float*)d_out;

    kernel_ab<<<BATCH, NTHREADS>>>(x, wq, bq, wk, bk, wv, bv,
                                   w1, b1, gamma, beta, mean, var);
    dim3 gc(TLEN / CT, BATCH);
    kernel_c<<<gc, CT>>>(x, w2, b2, out);
}

// round 3
// speedup vs baseline: 1.0965x; 1.0965x over previous
#include <cuda_runtime.h>

#define BATCH    512
#define TLEN     2048
#define CH       34      // true channel count (2*17)
#define P        36      // padded homogeneous dim (35 -> 36)
#define PP       37      // row pitch (bank-conflict-free)
#define TT       128     // t-tile for Gram phase
#define NBLK     45      // symmetric 4x4 blocks over 36 (9x9 grid, bc >= br)
#define TG       5       // threads (t-phases) per block
#define NTHREADS 256
#define CT       256     // t-chunk for pointwise kernel
#define NSPLIT   4       // t-splits for Gram kernel
#define TSPLIT   (TLEN / NSPLIT)

typedef unsigned long long ull;

// Per-batch fused head matrix: W1f[b][16][35] (homogeneous: col 34 = bias)
__device__ float g_W1f[BATCH * 16 * 35];
// Partial Gram matrices: g_part[b][s][36][36]
__device__ float g_part[BATCH * NSPLIT * P * P];

// ---------------- packed f32x2 helpers (sm_103a FFMA2) ----------------------

__device__ __forceinline__ ull pack2(float lo, float hi) {
    ull r; asm("mov.b64 %0, {%1, %2};" : "=l"(r) : "f"(lo), "f"(hi)); return r;
}
__device__ __forceinline__ void unpack2(ull v, float& lo, float& hi) {
    asm("mov.b64 {%0, %1}, %2;" : "=f"(lo), "=f"(hi) : "l"(v));
}
__device__ __forceinline__ void fma2(ull& d, ull a, ull b) {
    asm("fma.rn.f32x2 %0, %1, %2, %0;" : "+l"(d) : "l"(a), "l"(b));
}

// ---------------- 36x36 shared-memory matmuls (216 active threads) ----------

// D = A * B
__device__ __forceinline__ void mm_nn(float (*D)[PP], const float (*A)[PP],
                                      const float (*B)[PP], int tid) {
    if (tid < 216) {
        int r  = tid % P;
        int c0 = (tid / P) * 6;
        float a0 = 0.f, a1 = 0.f, a2 = 0.f, a3 = 0.f, a4 = 0.f, a5 = 0.f;
#pragma unroll
        for (int k = 0; k < P; k++) {
            float a = A[r][k];
            a0 += a * B[k][c0 + 0];
            a1 += a * B[k][c0 + 1];
            a2 += a * B[k][c0 + 2];
            a3 += a * B[k][c0 + 3];
            a4 += a * B[k][c0 + 4];
            a5 += a * B[k][c0 + 5];
        }
        D[r][c0 + 0] = a0; D[r][c0 + 1] = a1; D[r][c0 + 2] = a2;
        D[r][c0 + 3] = a3; D[r][c0 + 4] = a4; D[r][c0 + 5] = a5;
    }
    __syncthreads();
}

// D = A * B^T
__device__ __forceinline__ void mm_nt(float (*D)[PP], const float (*A)[PP],
                                      const float (*B)[PP], int tid) {
    if (tid < 216) {
        int r  = tid % P;
        int c0 = (tid / P) * 6;
        float a0 = 0.f, a1 = 0.f, a2 = 0.f, a3 = 0.f, a4 = 0.f, a5 = 0.f;
#pragma unroll
        for (int k = 0; k < P; k++) {
            float a = A[r][k];
            a0 += a * B[c0 + 0][k];
            a1 += a * B[c0 + 1][k];
            a2 += a * B[c0 + 2][k];
            a3 += a * B[c0 + 3][k];
            a4 += a * B[c0 + 4][k];
            a5 += a * B[c0 + 5][k];
        }
        D[r][c0 + 0] = a0; D[r][c0 + 1] = a1; D[r][c0 + 2] = a2;
        D[r][c0 + 3] = a3; D[r][c0 + 4] = a4; D[r][c0 + 5] = a5;
    }
    __syncthreads();
}

// Stage homogeneous weight: W[r<34][c<34] = w, W[r<34][34] = bias, W[34][34] = 1
__device__ __forceinline__ void stage_w(float (*W)[PP], const float* __restrict__ w,
                                        const float* __restrict__ bias, int tid) {
    for (int i = tid; i < P * PP; i += NTHREADS) {
        int r = i / PP, c = i % PP;
        float v = 0.f;
        if (r < CH && c < CH)       v = w[r * CH + c];
        else if (r < CH && c == CH) v = bias[r];
        else if (r == CH && c == CH) v = 1.f;
        W[r][c] = v;
    }
    __syncthreads();
}

// ---------------- Kernel GRAM: partial S over a t-split ---------------------

__global__ void __launch_bounds__(NTHREADS) kernel_gram(const float* __restrict__ x)
{
    __shared__ float S[P][PP];
    __shared__ __align__(16) float Hs[TT][P];

    int tid = threadIdx.x;
    int b   = blockIdx.x;
    int s   = blockIdx.y;

    for (int i = tid; i < P * PP; i += NTHREADS) (&S[0][0])[i] = 0.f;

    bool act = (tid < NBLK * TG);
    int br = 0, bc = 0, sub = 0;
    if (act) {
        int blk = tid / TG;
        sub = tid % TG;
        int k = blk, r = 0;
        while (k >= 9 - r) { k -= 9 - r; r++; }
        br = r; bc = r + k;
    }
    ull acc[8];
#pragma unroll
    for (int i = 0; i < 8; i++) acc[i] = 0ull;

    const float* xb = x + (size_t)b * 2 * TLEN * 17;
    int tbase = s * TSPLIT;

    for (int t0 = tbase; t0 < tbase + TSPLIT; t0 += TT) {
        __syncthreads();
#pragma unroll
        for (int c = 0; c < 2; c++) {
            const float* src = xb + (size_t)c * TLEN * 17 + (size_t)t0 * 17;
            for (int i = tid; i < TT * 17; i += NTHREADS)
                Hs[i / 17][c * 17 + i % 17] = src[i];
        }
        for (int i = tid; i < TT; i += NTHREADS) { Hs[i][34] = 1.f; Hs[i][35] = 0.f; }
        __syncthreads();

        if (act) {
            for (int t = sub; t < TT; t += TG) {
                float4 av  = *reinterpret_cast<const float4*>(&Hs[t][4 * br]);
                float4 bv4 = *reinterpret_cast<const float4*>(&Hs[t][4 * bc]);
                ull b01 = pack2(bv4.x, bv4.y);
                ull b23 = pack2(bv4.z, bv4.w);
                ull a0 = pack2(av.x, av.x);
                ull a1 = pack2(av.y, av.y);
                ull a2 = pack2(av.z, av.z);
                ull a3 = pack2(av.w, av.w);
                fma2(acc[0], a0, b01); fma2(acc[1], a0, b23);
                fma2(acc[2], a1, b01); fma2(acc[3], a1, b23);
                fma2(acc[4], a2, b01); fma2(acc[5], a2, b23);
                fma2(acc[6], a3, b01); fma2(acc[7], a3, b23);
            }
        }
    }
    __syncthreads();
    if (act) {
#pragma unroll
        for (int i = 0; i < 4; i++) {
            float v0, v1, v2, v3;
            unpack2(acc[2 * i + 0], v0, v1);
            unpack2(acc[2 * i + 1], v2, v3);
            atomicAdd(&S[4 * br + i][4 * bc + 0], v0);
            atomicAdd(&S[4 * br + i][4 * bc + 1], v1);
            atomicAdd(&S[4 * br + i][4 * bc + 2], v2);
            atomicAdd(&S[4 * br + i][4 * bc + 3], v3);
        }
    }
    __syncthreads();
    // mirror lower triangle
    for (int i = tid; i < P * P; i += NTHREADS) {
        int r = i / P, c = i % P;
        if (r > c) S[r][c] = S[c][r];
    }
    __syncthreads();
    float* dst = g_part + (size_t)(b * NSPLIT + s) * P * P;
    for (int i = tid; i < P * P; i += NTHREADS) dst[i] = S[i / P][i % P];
}

// ---------------- Kernel B: attention-layer math per batch ------------------

__global__ void __launch_bounds__(NTHREADS) kernel_b(
    const float* __restrict__ wq, const float* __restrict__ bq,
    const float* __restrict__ wk, const float* __restrict__ bk,
    const float* __restrict__ wv, const float* __restrict__ bv,
    const float* __restrict__ w1, const float* __restrict__ b1,
    const float* __restrict__ gamma, const float* __restrict__ beta,
    const float* __restrict__ mean, const float* __restrict__ var)
{
    __shared__ __align__(16) float smem[8][P][PP];
    float (*S)[PP]   = smem[0];
    float (*A)[PP]   = smem[1];
    float (*T1)[PP]  = smem[2];
    float (*G)[PP]   = smem[3];
    float (*M)[PP]   = smem[4];
    float (*W0)[PP]  = smem[5];
    float (*Wk_)[PP] = smem[6];
    float (*Wv_)[PP] = smem[7];

    int tid = threadIdx.x;
    int b   = blockIdx.x;

    // load + sum the 4 Gram partials
    const float* src = g_part + (size_t)b * NSPLIT * P * P;
    for (int i = tid; i < P * P; i += NTHREADS) {
        float v = src[i] + src[P * P + i] + src[2 * P * P + i] + src[3 * P * P + i];
        S[i / P][i % P] = v;
    }
    __syncthreads();

    float scale = rsqrtf((float)TLEN);

    for (int layer = 0; layer < 3; layer++) {
        stage_w(W0,  wq + layer * CH * CH, bq + layer * CH, tid);
        stage_w(Wk_, wk + layer * CH * CH, bk + layer * CH, tid);
        stage_w(Wv_, wv + layer * CH * CH, bv + layer * CH, tid);

        mm_nn(T1, W0, S, tid);    // T1 = Wq' S
        mm_nt(G, T1, Wk_, tid);   // G  = Wq' S Wk'^T  (= Q K^T incl. biases)

        // row softmax over d<34 with scale, then sanitize homogeneous rows
        if (tid < CH) {
            float mx = -1e30f;
            for (int c = 0; c < CH; c++) mx = fmaxf(mx, G[tid][c] * scale);
            float s = 0.f;
            for (int c = 0; c < CH; c++) {
                float e = expf(G[tid][c] * scale - mx);
                G[tid][c] = e; s += e;
            }
            float inv = 1.f / s;
            for (int c = 0; c < CH; c++) G[tid][c] *= inv;
            G[tid][34] = 0.f; G[tid][35] = 0.f;
        } else if (tid == CH) {
            for (int c = 0; c < PP; c++) { G[34][c] = 0.f; G[35][c] = 0.f; }
            G[34][34] = 1.f;
        }
        __syncthreads();

        mm_nn(M, G, Wv_, tid);    // M = attn' Wv''  (affine map for this layer)

        if (layer < 2) {          // propagate statistics: S <- M S M^T
            mm_nn(T1, M, S, tid);
            mm_nt(S, T1, M, tid);
        }

        if (layer == 0) {
            for (int i = tid; i < P * PP; i += NTHREADS) (&A[0][0])[i] = (&M[0][0])[i];
            __syncthreads();
        } else if (layer == 1) {
            mm_nn(T1, M, A, tid); // A <- M2 * M1
            for (int i = tid; i < P * PP; i += NTHREADS) (&A[0][0])[i] = (&T1[0][0])[i];
            __syncthreads();
        } else {
            // Fold conv1 + BatchNorm into homogeneous 16x35 W1h, stage into W0
            for (int i = tid; i < P * PP; i += NTHREADS) {
                int r = i / PP, c = i % PP;
                float v = 0.f;
                if (r < 16) {
                    float iv = gamma[r] * rsqrtf(var[r] + 1e-5f);
                    if (c < CH)       v = iv * w1[r * CH + c];
                    else if (c == CH) v = iv * (b1[r] - mean[r]) + beta[r];
                }
                W0[r][c] = v;
            }
            __syncthreads();
            mm_nn(T1, W0, M, tid); // R   = W1h * M3
            mm_nn(G, T1, A, tid);  // W1f = R * (M2 M1)
            for (int i = tid; i < 16 * 35; i += NTHREADS)
                g_W1f[b * 16 * 35 + i] = G[i / 35][i % 35];
        }
    }
}

// ---------------- Kernel C: pointwise head over every (b, t) ----------------

__global__ void __launch_bounds__(CT, 4) kernel_c(
    const float* __restrict__ x,
    const float* __restrict__ w2, const float* __restrict__ b2,
    float* __restrict__ out)
{
    __shared__ __align__(16) float Wt[35][16];   // transposed W1f: Wt[c][o]
    __shared__ float w2s[48];
    __shared__ float b2s[3];
    __shared__ float Hc[CT][37];   // pitch 37 -> conflict-free column reads

    int tid = threadIdx.x;
    int b   = blockIdx.y;
    int t0  = blockIdx.x * CT;

    for (int i = tid; i < 16 * 35; i += CT) {
        int c = i / 16, o = i % 16;
        Wt[c][o] = g_W1f[b * 16 * 35 + o * 35 + c];
    }
    if (tid < 48) w2s[tid] = w2[tid];
    if (tid < 3)  b2s[tid] = b2[tid];
#pragma unroll
    for (int c = 0; c < 2; c++) {
        const float* src = x + ((size_t)(b * 2 + c) * TLEN + t0) * 17;
        for (int i = tid; i < CT * 17; i += CT)
            Hc[i / 17][c * 17 + i % 17] = src[i];
    }
    __syncthreads();

    ull u[8];
    {
        const ull* wb = reinterpret_cast<const ull*>(&Wt[34][0]);
#pragma unroll
        for (int p = 0; p < 8; p++) u[p] = wb[p];   // homogeneous bias column
    }
#pragma unroll
    for (int c = 0; c < CH; c++) {
        float hv = Hc[tid][c];
        ull hh = pack2(hv, hv);
        const ull* wr = reinterpret_cast<const ull*>(&Wt[c][0]);
#pragma unroll
        for (int p = 0; p < 8; p++) fma2(u[p], wr[p], hh);
    }

    float uf[16];
#pragma unroll
    for (int p = 0; p < 8; p++) unpack2(u[p], uf[2 * p], uf[2 * p + 1]);
#pragma unroll
    for (int o = 0; o < 16; o++) uf[o] = (uf[o] > 0.f) ? uf[o] : 0.01f * uf[o];

#pragma unroll
    for (int j = 0; j < 3; j++) {
        float s = b2s[j];
#pragma unroll
        for (int o = 0; o < 16; o++) s += w2s[j * 16 + o] * uf[o];
        out[(size_t)(b * 3 + j) * TLEN + t0 + tid] = s;
    }
}

// ---------------------------------------------------------------------------

extern "C" void kernel_launch(void* const* d_in, const int* in_sizes, int n_in,
                              void* d_out, int out_size) {
    const float* x     = (const float*)d_in[0];
    const float* wq    = (const float*)d_in[1];
    const float* bq    = (const float*)d_in[2];
    const float* wk    = (const float*)d_in[3];
    const float* bk    = (const float*)d_in[4];
    const float* wv    = (const float*)d_in[5];
    const float* bv    = (const float*)d_in[6];
    const float* w1    = (const float*)d_in[7];
    const float* b1    = (const float*)d_in[8];
    const float* gamma = (const float*)d_in[9];
    const float* beta  = (const float*)d_in[10];
    const float* mean  = (const float*)d_in[11];
    const float* var   = (const float*)d_in[12];
    const float* w2    = (const float*)d_in[13];
    const float* b2    = (const float*)d_in[14];
    float* out = (float*)d_out;

    dim3 gg(BATCH, NSPLIT);
    kernel_gram<<<gg, NTHREADS>>>(x);
    kernel_b<<<BATCH, NTHREADS>>>(wq, bq, wk, bk, wv, bv,
                                  w1, b1, gamma, beta, mean, var);
    dim3 gc(TLEN / CT, BATCH);
    kernel_c<<<gc, CT>>>(x, w2, b2, out);
}